// round 13
// baseline (speedup 1.0000x reference)
#include <cuda_runtime.h>
#include <cuda_bf16.h>
#include <cuda_fp16.h>
#include <mma.h>
#include <cstdint>

using namespace nvcuda;

#define NN 100000
#define NN_PAD 100096        // 782 * 128, store-tail padding
#define EE 1600000
#define NT64 (EE / 64)       // 25000 64-edge tiles, exact
#define NPT 782              // node tiles of 128

__device__ __align__(256) float g_A[NN_PAD * 64];   // (W1a - W1b) @ x[n] + b1
__device__ __align__(256) float g_B[NN_PAD * 64];   // W1b @ x[n]

extern __shared__ __align__(16) char dynsm[];

static __device__ __forceinline__ uint32_t pack_bf2(__nv_bfloat16 a, __nv_bfloat16 b) {
    __nv_bfloat162 v = __halves2bfloat162(a, b);
    return *reinterpret_cast<uint32_t*>(&v);
}

// ---------------------------------------------------------------------------
// Pre kernel (unchanged from R12): wmma bf16 3-term, fp32 A/B tables.
// ---------------------------------------------------------------------------
#define PHSTR 88
#define PPLANE 22528                         // 128*88*2 bytes
#define PRE_SMEM (2 * PPLANE)                // 45056

__global__ void __launch_bounds__(256)
pre_kernel(const float* __restrict__ x, const float* __restrict__ W1,
           const float* __restrict__ b1) {
    __nv_bfloat16* ph = (__nv_bfloat16*)(dynsm);
    __nv_bfloat16* pl = (__nv_bfloat16*)(dynsm + PPLANE);

    const int t = threadIdx.x;
    const int w = t >> 5;
    const int rh = w >> 2;
    const int nh = w & 3;

    {
        int j = t & 127, kh = t >> 7;
        if (kh == 0) {
#pragma unroll
            for (int k = 0; k < 32; k++) {
                float f = (j < 64)
                    ? __ldg(W1 + j * 128 + k) - __ldg(W1 + j * 128 + 64 + k)
                    : __ldg(W1 + (j - 64) * 128 + 64 + k);
                __nv_bfloat16 hi = __float2bfloat16(f);
                ph[j * PHSTR + k] = hi;
                pl[j * PHSTR + k] = __float2bfloat16(f - __bfloat162float(hi));
            }
        } else {
#pragma unroll
            for (int k = 32; k < 64; k++) {
                float f = (j < 64)
                    ? __ldg(W1 + j * 128 + k) - __ldg(W1 + j * 128 + 64 + k)
                    : __ldg(W1 + (j - 64) * 128 + 64 + k);
                __nv_bfloat16 hi = __float2bfloat16(f);
                ph[j * PHSTR + k] = hi;
                pl[j * PHSTR + k] = __float2bfloat16(f - __bfloat162float(hi));
            }
            float bf = (j < 64) ? __ldg(b1 + j) : 0.f;
            __nv_bfloat16 bh = __float2bfloat16(bf);
            ph[j * PHSTR + 64] = bh;
            pl[j * PHSTR + 64] = __float2bfloat16(bf - __bfloat162float(bh));
#pragma unroll
            for (int k = 65; k < 80; k++) {
                ph[j * PHSTR + k] = __float2bfloat16(0.f);
                pl[j * PHSTR + k] = __float2bfloat16(0.f);
            }
        }
    }
    __syncthreads();

    wmma::fragment<wmma::matrix_b, 16, 16, 16, __nv_bfloat16, wmma::col_major>
        Bh[4][2], Bl[4][2], Bbh[2], Bbl[2];
#pragma unroll
    for (int ks = 0; ks < 4; ks++)
#pragma unroll
        for (int q = 0; q < 2; q++) {
            int j0 = (nh * 32 + q * 16) * PHSTR;
            wmma::load_matrix_sync(Bh[ks][q], ph + j0 + ks * 16, PHSTR);
            wmma::load_matrix_sync(Bl[ks][q], pl + j0 + ks * 16, PHSTR);
        }
#pragma unroll
    for (int q = 0; q < 2; q++) {
        int j0 = (nh * 32 + q * 16) * PHSTR;
        wmma::load_matrix_sync(Bbh[q], ph + j0 + 64, PHSTR);
        wmma::load_matrix_sync(Bbl[q], pl + j0 + 64, PHSTR);
    }
    __syncthreads();

    if (t < 128) {
        ph[t * PHSTR + 64] = __float2bfloat16(1.f);
        pl[t * PHSTR + 64] = __float2bfloat16(0.f);
#pragma unroll
        for (int k = 65; k < 80; k++) {
            ph[t * PHSTR + k] = __float2bfloat16(0.f);
            pl[t * PHSTR + k] = __float2bfloat16(0.f);
        }
    }

    const int xr = t >> 4;
    const int g  = t & 15;

    for (int tile = blockIdx.x; tile < NPT; tile += gridDim.x) {
        int node0 = tile * 128;
        __syncthreads();

#pragma unroll
        for (int p = 0; p < 8; p++) {
            int row = p * 16 + xr;
            int node = node0 + row;
            float4 v = make_float4(0.f, 0.f, 0.f, 0.f);
            if (node < NN) v = __ldg((const float4*)(x + (size_t)node * 64) + g);
            __nv_bfloat16 h0 = __float2bfloat16(v.x), h1 = __float2bfloat16(v.y);
            __nv_bfloat16 h2 = __float2bfloat16(v.z), h3 = __float2bfloat16(v.w);
            uint2 hi = make_uint2(pack_bf2(h0, h1), pack_bf2(h2, h3));
            uint2 lo = make_uint2(
                pack_bf2(__float2bfloat16(v.x - __bfloat162float(h0)),
                         __float2bfloat16(v.y - __bfloat162float(h1))),
                pack_bf2(__float2bfloat16(v.z - __bfloat162float(h2)),
                         __float2bfloat16(v.w - __bfloat162float(h3))));
            *(uint2*)(ph + row * PHSTR + g * 4) = hi;
            *(uint2*)(pl + row * PHSTR + g * 4) = lo;
        }
        __syncthreads();

        float* tbase = (nh < 2) ? (g_A + nh * 32) : (g_B + (nh - 2) * 32);
#pragma unroll
        for (int rbp = 0; rbp < 4; rbp++) {
            int rows = rh * 64 + rbp * 16;

            wmma::fragment<wmma::accumulator, 16, 16, 16, float> acc0, acc1;
            wmma::fill_fragment(acc0, 0.f);
            wmma::fill_fragment(acc1, 0.f);

            wmma::fragment<wmma::matrix_a, 16, 16, 16, __nv_bfloat16, wmma::row_major> ah, al;

#pragma unroll
            for (int ks = 0; ks < 4; ks++) {
                wmma::load_matrix_sync(ah, ph + rows * PHSTR + ks * 16, PHSTR);
                wmma::load_matrix_sync(al, pl + rows * PHSTR + ks * 16, PHSTR);
                wmma::mma_sync(acc0, ah, Bh[ks][0], acc0);
                wmma::mma_sync(acc1, ah, Bh[ks][1], acc1);
                wmma::mma_sync(acc0, ah, Bl[ks][0], acc0);
                wmma::mma_sync(acc1, ah, Bl[ks][1], acc1);
                wmma::mma_sync(acc0, al, Bh[ks][0], acc0);
                wmma::mma_sync(acc1, al, Bh[ks][1], acc1);
            }
            wmma::load_matrix_sync(ah, ph + rows * PHSTR + 64, PHSTR);
            wmma::mma_sync(acc0, ah, Bbh[0], acc0);
            wmma::mma_sync(acc1, ah, Bbh[1], acc1);
            wmma::mma_sync(acc0, ah, Bbl[0], acc0);
            wmma::mma_sync(acc1, ah, Bbl[1], acc1);

            float* op = tbase + (size_t)(node0 + rows) * 64;
            wmma::store_matrix_sync(op, acc0, 64, wmma::mem_row_major);
            wmma::store_matrix_sync(op + 16, acc1, 64, wmma::mem_row_major);
        }
    }
}

// ---------------------------------------------------------------------------
// Edge kernel v5: fp16 asymmetric split + smem-staged coalesced output.
//  - h: SINGLE fp16 plane (no lo).  W2: 2-term fp16 (wh + wl, err 2^-22).
//    out = Ah*Bh + Ah*Bl  (+ bias block).  Expected rel_err ~3e-4.
//  - warp (rh, nh): rows rh*32..+32, cols nh*32..+32; B frags in registers.
//  - output: acc -> per-warp smem stage (ld=36, conflict-free) -> coalesced
//    STG.128 sweep (512B contiguous per warp-instr), overlapped with next
//    tile's gather between the same two syncs.
// K layout: 0..63 data, 64 = ones (bias), 65..79 zero pad.
// ---------------------------------------------------------------------------
#define HSTR 88
#define OFF_HH   0                       // 64*88*2  = 11264 (also w2h at init)
#define OFF_STG  11520                   // 4 warps * 4608 = 18432 (w2l at init)
#define STG_WSTR 1152                    // floats per warp stage region (32*36)
#define EDGE_SMEM 30208

__global__ void __launch_bounds__(128, 4)
edge_kernel(const int* __restrict__ ei, const float* __restrict__ W2,
            const float* __restrict__ b2, float* __restrict__ out) {
    __half* hh    = (__half*)(dynsm + OFF_HH);
    float*  stg   = (float*)(dynsm + OFF_STG);

    const int t = threadIdx.x;
    const int w = t >> 5;
    const int rh = w >> 1;         // rows rh*32..+32
    const int nh = w & 1;          // cols nh*32..+32

    // ---- init: stage W2 hi/lo fp16 (col j = B-operand row), load frags ----
    {
        __half* w2h = hh;                       // 64*88*2 = 11264 B
        __half* w2l = (__half*)(dynsm + OFF_STG);
        if (t < 64) {
            int j = t;
#pragma unroll
            for (int k = 0; k < 64; k++) {
                float f = __ldg(W2 + j * 64 + k);
                __half hi = __float2half_rn(f);
                w2h[j * HSTR + k] = hi;
                w2l[j * HSTR + k] = __float2half_rn(f - __half2float(hi));
            }
            float bf = __ldg(b2 + j);
            __half bh = __float2half_rn(bf);
            w2h[j * HSTR + 64] = bh;
            w2l[j * HSTR + 64] = __float2half_rn(bf - __half2float(bh));
#pragma unroll
            for (int k = 65; k < 80; k++) {
                w2h[j * HSTR + k] = __float2half_rn(0.f);
                w2l[j * HSTR + k] = __float2half_rn(0.f);
            }
        }
        __syncthreads();

        // fragments loaded below from w2h/w2l
    }

    wmma::fragment<wmma::matrix_b, 16, 16, 16, __half, wmma::col_major>
        Bh[4][2], Bl[4][2], Bbh[2], Bbl[2];
    {
        const __half* w2h = hh;
        const __half* w2l = (const __half*)(dynsm + OFF_STG);
#pragma unroll
        for (int ks = 0; ks < 4; ks++)
#pragma unroll
            for (int q = 0; q < 2; q++) {
                int j0 = (nh * 32 + q * 16) * HSTR;
                wmma::load_matrix_sync(Bh[ks][q], w2h + j0 + ks * 16, HSTR);
                wmma::load_matrix_sync(Bl[ks][q], w2l + j0 + ks * 16, HSTR);
            }
#pragma unroll
        for (int q = 0; q < 2; q++) {
            int j0 = (nh * 32 + q * 16) * HSTR;
            wmma::load_matrix_sync(Bbh[q], w2h + j0 + 64, HSTR);
            wmma::load_matrix_sync(Bbl[q], w2l + j0 + 64, HSTR);
        }
    }
    __syncthreads();

    // ---- one-time: h pad columns (64 = ones, 65..79 = zero) ----
    if (t < 64) {
        hh[t * HSTR + 64] = __float2half_rn(1.f);
#pragma unroll
        for (int k = 65; k < 80; k++)
            hh[t * HSTR + k] = __float2half_rn(0.f);
    }

    const int grp = t >> 4;        // 8 groups of 16 threads
    const int g   = t & 15;

    // gather one tile's h into the fp16 plane (coalesced, no lo)
    auto gather = [&](int tile) {
#pragma unroll
        for (int p = 0; p < 8; p++) {
            int edge = p * 8 + grp;
            int r = __ldg(ei + tile * 64 + edge);
            int c = __ldg(ei + EE + tile * 64 + edge);
            float4 a = __ldg((const float4*)(g_A + (size_t)r * 64) + g);
            float4 b = __ldg((const float4*)(g_B + (size_t)c * 64) + g);
            __half2 p0 = __floats2half2_rn(fmaxf(a.x + b.x, 0.f),
                                           fmaxf(a.y + b.y, 0.f));
            __half2 p1 = __floats2half2_rn(fmaxf(a.z + b.z, 0.f),
                                           fmaxf(a.w + b.w, 0.f));
            *(uint2*)(hh + edge * HSTR + g * 4) =
                make_uint2(*(uint32_t*)&p0, *(uint32_t*)&p1);
        }
    };

    int tile = blockIdx.x;
    if (tile < NT64) gather(tile);
    __syncthreads();

    while (tile < NT64) {
        // ---- compute: warp (rh, nh); 2 x 16-row blocks; stage to smem ----
        float* wstg = stg + w * STG_WSTR;
#pragma unroll
        for (int rbp = 0; rbp < 2; rbp++) {
            int rows = rh * 32 + rbp * 16;

            wmma::fragment<wmma::accumulator, 16, 16, 16, float> acc0, acc1;
            wmma::fill_fragment(acc0, 0.f);
            wmma::fill_fragment(acc1, 0.f);

            wmma::fragment<wmma::matrix_a, 16, 16, 16, __half, wmma::row_major> ah;

#pragma unroll
            for (int ks = 0; ks < 4; ks++) {
                wmma::load_matrix_sync(ah, hh + rows * HSTR + ks * 16, HSTR);
                wmma::mma_sync(acc0, ah, Bh[ks][0], acc0);
                wmma::mma_sync(acc1, ah, Bh[ks][1], acc1);
                wmma::mma_sync(acc0, ah, Bl[ks][0], acc0);
                wmma::mma_sync(acc1, ah, Bl[ks][1], acc1);
            }
            wmma::load_matrix_sync(ah, hh + rows * HSTR + 64, HSTR);
            wmma::mma_sync(acc0, ah, Bbh[0], acc0);
            wmma::mma_sync(acc1, ah, Bbh[1], acc1);
            wmma::mma_sync(acc0, ah, Bbl[0], acc0);
            wmma::mma_sync(acc1, ah, Bbl[1], acc1);

#pragma unroll
            for (int i = 0; i < acc0.num_elements; i++) {
                acc0.x[i] = fmaxf(acc0.x[i], 0.f);
                acc1.x[i] = fmaxf(acc1.x[i], 0.f);
            }
            // stage: local rows rbp*16..+16, local cols 0..32, ld=36
            wmma::store_matrix_sync(wstg + rbp * 16 * 36, acc0, 36,
                                    wmma::mem_row_major);
            wmma::store_matrix_sync(wstg + rbp * 16 * 36 + 16, acc1, 36,
                                    wmma::mem_row_major);
        }
        __syncthreads();   // stage complete; hh free

        // ---- coalesced STG sweep (reads stage) + next tile gather (hh) ----
        int next = tile + gridDim.x;
        {
            float* op = out + (size_t)tile * 64 * 64;   // tile*64 edges * 64
#pragma unroll
            for (int p = 0; p < 8; p++) {
                int R = p * 8 + (t >> 4);      // 0..63
                int C = g * 4;                  // 0..60
                int ws = ((R >> 5) << 1) + (C >> 5);
                const float* src = stg + ws * STG_WSTR + (R & 31) * 36 + (C & 31);
                float4 v = make_float4(src[0], src[1], src[2], src[3]);
                *(float4*)(op + R * 64 + C) = v;
            }
        }
        if (next < NT64) gather(next);
        __syncthreads();   // STG reads done + gather visible before reuse
        tile = next;
    }
}

// ---------------------------------------------------------------------------
extern "C" void kernel_launch(void* const* d_in, const int* in_sizes, int n_in,
                              void* d_out, int out_size) {
    const float* x  = (const float*)d_in[0];
    const int*   ei = (const int*)d_in[1];     // int32 (JAX x64 disabled)
    const float* W1 = (const float*)d_in[2];
    const float* b1 = (const float*)d_in[3];
    const float* W2 = (const float*)d_in[4];
    const float* b2 = (const float*)d_in[5];
    float*       out = (float*)d_out;

    cudaFuncSetAttribute(pre_kernel,
                         cudaFuncAttributeMaxDynamicSharedMemorySize, PRE_SMEM);
    cudaFuncSetAttribute(edge_kernel,
                         cudaFuncAttributeMaxDynamicSharedMemorySize, EDGE_SMEM);

    pre_kernel<<<296, 256, PRE_SMEM>>>(x, W1, b1);
    edge_kernel<<<592, 128, EDGE_SMEM>>>(ei, W2, b2, out);
}

// round 16
// speedup vs baseline: 1.1954x; 1.1954x over previous
#include <cuda_runtime.h>
#include <cuda_bf16.h>
#include <cuda_fp16.h>
#include <mma.h>
#include <cstdint>

using namespace nvcuda;

#define NN 100000
#define NN_PAD 100096        // 782 * 128, store-tail padding
#define EE 1600000
#define NT64 (EE / 64)       // 25000 64-edge tiles, exact
#define NPT 782              // node tiles of 128

__device__ __align__(256) float g_A[NN_PAD * 64];   // (W1a - W1b) @ x[n] + b1
__device__ __align__(256) float g_B[NN_PAD * 64];   // W1b @ x[n]

extern __shared__ __align__(16) char dynsm[];

static __device__ __forceinline__ uint32_t pack_bf2(__nv_bfloat16 a, __nv_bfloat16 b) {
    __nv_bfloat162 v = __halves2bfloat162(a, b);
    return *reinterpret_cast<uint32_t*>(&v);
}

// ---------------------------------------------------------------------------
// Pre kernel (unchanged from R12): wmma bf16 3-term, fp32 A/B tables.
// ---------------------------------------------------------------------------
#define PHSTR 88
#define PPLANE 22528                         // 128*88*2 bytes
#define PRE_SMEM (2 * PPLANE)                // 45056

__global__ void __launch_bounds__(256)
pre_kernel(const float* __restrict__ x, const float* __restrict__ W1,
           const float* __restrict__ b1) {
    __nv_bfloat16* ph = (__nv_bfloat16*)(dynsm);
    __nv_bfloat16* pl = (__nv_bfloat16*)(dynsm + PPLANE);

    const int t = threadIdx.x;
    const int w = t >> 5;
    const int rh = w >> 2;
    const int nh = w & 3;

    {
        int j = t & 127, kh = t >> 7;
        if (kh == 0) {
#pragma unroll
            for (int k = 0; k < 32; k++) {
                float f = (j < 64)
                    ? __ldg(W1 + j * 128 + k) - __ldg(W1 + j * 128 + 64 + k)
                    : __ldg(W1 + (j - 64) * 128 + 64 + k);
                __nv_bfloat16 hi = __float2bfloat16(f);
                ph[j * PHSTR + k] = hi;
                pl[j * PHSTR + k] = __float2bfloat16(f - __bfloat162float(hi));
            }
        } else {
#pragma unroll
            for (int k = 32; k < 64; k++) {
                float f = (j < 64)
                    ? __ldg(W1 + j * 128 + k) - __ldg(W1 + j * 128 + 64 + k)
                    : __ldg(W1 + (j - 64) * 128 + 64 + k);
                __nv_bfloat16 hi = __float2bfloat16(f);
                ph[j * PHSTR + k] = hi;
                pl[j * PHSTR + k] = __float2bfloat16(f - __bfloat162float(hi));
            }
            float bf = (j < 64) ? __ldg(b1 + j) : 0.f;
            __nv_bfloat16 bh = __float2bfloat16(bf);
            ph[j * PHSTR + 64] = bh;
            pl[j * PHSTR + 64] = __float2bfloat16(bf - __bfloat162float(bh));
#pragma unroll
            for (int k = 65; k < 80; k++) {
                ph[j * PHSTR + k] = __float2bfloat16(0.f);
                pl[j * PHSTR + k] = __float2bfloat16(0.f);
            }
        }
    }
    __syncthreads();

    wmma::fragment<wmma::matrix_b, 16, 16, 16, __nv_bfloat16, wmma::col_major>
        Bh[4][2], Bl[4][2], Bbh[2], Bbl[2];
#pragma unroll
    for (int ks = 0; ks < 4; ks++)
#pragma unroll
        for (int q = 0; q < 2; q++) {
            int j0 = (nh * 32 + q * 16) * PHSTR;
            wmma::load_matrix_sync(Bh[ks][q], ph + j0 + ks * 16, PHSTR);
            wmma::load_matrix_sync(Bl[ks][q], pl + j0 + ks * 16, PHSTR);
        }
#pragma unroll
    for (int q = 0; q < 2; q++) {
        int j0 = (nh * 32 + q * 16) * PHSTR;
        wmma::load_matrix_sync(Bbh[q], ph + j0 + 64, PHSTR);
        wmma::load_matrix_sync(Bbl[q], pl + j0 + 64, PHSTR);
    }
    __syncthreads();

    if (t < 128) {
        ph[t * PHSTR + 64] = __float2bfloat16(1.f);
        pl[t * PHSTR + 64] = __float2bfloat16(0.f);
#pragma unroll
        for (int k = 65; k < 80; k++) {
            ph[t * PHSTR + k] = __float2bfloat16(0.f);
            pl[t * PHSTR + k] = __float2bfloat16(0.f);
        }
    }

    const int xr = t >> 4;
    const int g  = t & 15;

    for (int tile = blockIdx.x; tile < NPT; tile += gridDim.x) {
        int node0 = tile * 128;
        __syncthreads();

#pragma unroll
        for (int p = 0; p < 8; p++) {
            int row = p * 16 + xr;
            int node = node0 + row;
            float4 v = make_float4(0.f, 0.f, 0.f, 0.f);
            if (node < NN) v = __ldg((const float4*)(x + (size_t)node * 64) + g);
            __nv_bfloat16 h0 = __float2bfloat16(v.x), h1 = __float2bfloat16(v.y);
            __nv_bfloat16 h2 = __float2bfloat16(v.z), h3 = __float2bfloat16(v.w);
            uint2 hi = make_uint2(pack_bf2(h0, h1), pack_bf2(h2, h3));
            uint2 lo = make_uint2(
                pack_bf2(__float2bfloat16(v.x - __bfloat162float(h0)),
                         __float2bfloat16(v.y - __bfloat162float(h1))),
                pack_bf2(__float2bfloat16(v.z - __bfloat162float(h2)),
                         __float2bfloat16(v.w - __bfloat162float(h3))));
            *(uint2*)(ph + row * PHSTR + g * 4) = hi;
            *(uint2*)(pl + row * PHSTR + g * 4) = lo;
        }
        __syncthreads();

        float* tbase = (nh < 2) ? (g_A + nh * 32) : (g_B + (nh - 2) * 32);
#pragma unroll
        for (int rbp = 0; rbp < 4; rbp++) {
            int rows = rh * 64 + rbp * 16;

            wmma::fragment<wmma::accumulator, 16, 16, 16, float> acc0, acc1;
            wmma::fill_fragment(acc0, 0.f);
            wmma::fill_fragment(acc1, 0.f);

            wmma::fragment<wmma::matrix_a, 16, 16, 16, __nv_bfloat16, wmma::row_major> ah, al;

#pragma unroll
            for (int ks = 0; ks < 4; ks++) {
                wmma::load_matrix_sync(ah, ph + rows * PHSTR + ks * 16, PHSTR);
                wmma::load_matrix_sync(al, pl + rows * PHSTR + ks * 16, PHSTR);
                wmma::mma_sync(acc0, ah, Bh[ks][0], acc0);
                wmma::mma_sync(acc1, ah, Bh[ks][1], acc1);
                wmma::mma_sync(acc0, ah, Bl[ks][0], acc0);
                wmma::mma_sync(acc1, ah, Bl[ks][1], acc1);
                wmma::mma_sync(acc0, al, Bh[ks][0], acc0);
                wmma::mma_sync(acc1, al, Bh[ks][1], acc1);
            }
            wmma::load_matrix_sync(ah, ph + rows * PHSTR + 64, PHSTR);
            wmma::mma_sync(acc0, ah, Bbh[0], acc0);
            wmma::mma_sync(acc1, ah, Bbh[1], acc1);
            wmma::mma_sync(acc0, ah, Bbl[0], acc0);
            wmma::mma_sync(acc1, ah, Bbl[1], acc1);

            float* op = tbase + (size_t)(node0 + rows) * 64;
            wmma::store_matrix_sync(op, acc0, 64, wmma::mem_row_major);
            wmma::store_matrix_sync(op + 16, acc1, 64, wmma::mem_row_major);
        }
    }
}

// ---------------------------------------------------------------------------
// Edge kernel v6 = R12 structure + R13 numerics.
//  - h: SINGLE fp16 plane; W2: 2-term fp16 (wh + wl); out = Ah*Bh + Ah*Bl.
//  - direct store_matrix_sync to gmem (no smem staging — R13 falsified that).
//  - warp (rh, nh): rows rh*32..+32, cols nh*32..+32; B frags in registers.
//  - 2 __syncthreads per tile, 4 blocks/SM.
// K layout: 0..63 data, 64 = ones (bias), 65..79 zero pad.
// ---------------------------------------------------------------------------
#define HSTR 88
#define OFF_HH   0                       // 64*88*2 = 11264 (w2h during init)
#define OFF_W2L  11264                   // 11264 (w2l temp during init only)
#define EDGE_SMEM 22784

__global__ void __launch_bounds__(128, 4)
edge_kernel(const int* __restrict__ ei, const float* __restrict__ W2,
            const float* __restrict__ b2, float* __restrict__ out) {
    __half* hh = (__half*)(dynsm + OFF_HH);

    const int t = threadIdx.x;
    const int w = t >> 5;
    const int rh = w >> 1;         // rows rh*32..+32
    const int nh = w & 1;          // cols nh*32..+32

    // ---- init: stage W2 hi/lo fp16 (col j = B-operand row) ----
    {
        __half* w2h = hh;
        __half* w2l = (__half*)(dynsm + OFF_W2L);
        if (t < 64) {
            int j = t;
#pragma unroll
            for (int k = 0; k < 64; k++) {
                float f = __ldg(W2 + j * 64 + k);
                __half hi = __float2half_rn(f);
                w2h[j * HSTR + k] = hi;
                w2l[j * HSTR + k] = __float2half_rn(f - __half2float(hi));
            }
            float bf = __ldg(b2 + j);
            __half bh = __float2half_rn(bf);
            w2h[j * HSTR + 64] = bh;
            w2l[j * HSTR + 64] = __float2half_rn(bf - __half2float(bh));
#pragma unroll
            for (int k = 65; k < 80; k++) {
                w2h[j * HSTR + k] = __float2half_rn(0.f);
                w2l[j * HSTR + k] = __float2half_rn(0.f);
            }
        }
        __syncthreads();
    }

    wmma::fragment<wmma::matrix_b, 16, 16, 16, __half, wmma::col_major>
        Bh[4][2], Bl[4][2], Bbh[2], Bbl[2];
    {
        const __half* w2h = hh;
        const __half* w2l = (const __half*)(dynsm + OFF_W2L);
#pragma unroll
        for (int ks = 0; ks < 4; ks++)
#pragma unroll
            for (int q = 0; q < 2; q++) {
                int j0 = (nh * 32 + q * 16) * HSTR;
                wmma::load_matrix_sync(Bh[ks][q], w2h + j0 + ks * 16, HSTR);
                wmma::load_matrix_sync(Bl[ks][q], w2l + j0 + ks * 16, HSTR);
            }
#pragma unroll
        for (int q = 0; q < 2; q++) {
            int j0 = (nh * 32 + q * 16) * HSTR;
            wmma::load_matrix_sync(Bbh[q], w2h + j0 + 64, HSTR);
            wmma::load_matrix_sync(Bbl[q], w2l + j0 + 64, HSTR);
        }
    }
    __syncthreads();

    // ---- one-time: h pad columns (64 = ones, 65..79 = zero) ----
    if (t < 64) {
        hh[t * HSTR + 64] = __float2half_rn(1.f);
#pragma unroll
        for (int k = 65; k < 80; k++)
            hh[t * HSTR + k] = __float2half_rn(0.f);
    }
    __syncthreads();

    const int grp = t >> 4;        // 8 groups of 16 threads
    const int g   = t & 15;

    for (int tile = blockIdx.x; tile < NT64; tile += gridDim.x) {
        // ---- gather: coalesced, single fp16 plane ----
#pragma unroll
        for (int p = 0; p < 8; p++) {
            int edge = p * 8 + grp;
            int r = __ldg(ei + tile * 64 + edge);
            int c = __ldg(ei + EE + tile * 64 + edge);
            float4 a = __ldg((const float4*)(g_A + (size_t)r * 64) + g);
            float4 b = __ldg((const float4*)(g_B + (size_t)c * 64) + g);
            __half2 p0 = __floats2half2_rn(fmaxf(a.x + b.x, 0.f),
                                           fmaxf(a.y + b.y, 0.f));
            __half2 p1 = __floats2half2_rn(fmaxf(a.z + b.z, 0.f),
                                           fmaxf(a.w + b.w, 0.f));
            *(uint2*)(hh + edge * HSTR + g * 4) =
                make_uint2(*(uint32_t*)&p0, *(uint32_t*)&p1);
        }
        __syncthreads();

        // ---- compute: warp (rh, nh); 2 x 16-row blocks; direct gmem store ----
#pragma unroll
        for (int rbp = 0; rbp < 2; rbp++) {
            int rows = rh * 32 + rbp * 16;

            wmma::fragment<wmma::accumulator, 16, 16, 16, float> acc0, acc1;
            wmma::fill_fragment(acc0, 0.f);
            wmma::fill_fragment(acc1, 0.f);

            wmma::fragment<wmma::matrix_a, 16, 16, 16, __half, wmma::row_major> ah;

#pragma unroll
            for (int ks = 0; ks < 4; ks++) {
                wmma::load_matrix_sync(ah, hh + rows * HSTR + ks * 16, HSTR);
                wmma::mma_sync(acc0, ah, Bh[ks][0], acc0);
                wmma::mma_sync(acc1, ah, Bh[ks][1], acc1);
                wmma::mma_sync(acc0, ah, Bl[ks][0], acc0);
                wmma::mma_sync(acc1, ah, Bl[ks][1], acc1);
            }
            wmma::load_matrix_sync(ah, hh + rows * HSTR + 64, HSTR);
            wmma::mma_sync(acc0, ah, Bbh[0], acc0);
            wmma::mma_sync(acc1, ah, Bbh[1], acc1);
            wmma::mma_sync(acc0, ah, Bbl[0], acc0);
            wmma::mma_sync(acc1, ah, Bbl[1], acc1);

#pragma unroll
            for (int i = 0; i < acc0.num_elements; i++) {
                acc0.x[i] = fmaxf(acc0.x[i], 0.f);
                acc1.x[i] = fmaxf(acc1.x[i], 0.f);
            }
            float* op = out + (size_t)(tile * 64 + rows) * 64 + nh * 32;
            wmma::store_matrix_sync(op, acc0, 64, wmma::mem_row_major);
            wmma::store_matrix_sync(op + 16, acc1, 64, wmma::mem_row_major);
        }
        __syncthreads();   // compute done before next tile's gather overwrites
    }
}

// ---------------------------------------------------------------------------
extern "C" void kernel_launch(void* const* d_in, const int* in_sizes, int n_in,
                              void* d_out, int out_size) {
    const float* x  = (const float*)d_in[0];
    const int*   ei = (const int*)d_in[1];     // int32 (JAX x64 disabled)
    const float* W1 = (const float*)d_in[2];
    const float* b1 = (const float*)d_in[3];
    const float* W2 = (const float*)d_in[4];
    const float* b2 = (const float*)d_in[5];
    float*       out = (float*)d_out;

    cudaFuncSetAttribute(pre_kernel,
                         cudaFuncAttributeMaxDynamicSharedMemorySize, PRE_SMEM);
    cudaFuncSetAttribute(edge_kernel,
                         cudaFuncAttributeMaxDynamicSharedMemorySize, EDGE_SMEM);

    pre_kernel<<<296, 256, PRE_SMEM>>>(x, W1, b1);
    edge_kernel<<<592, 128, EDGE_SMEM>>>(ei, W2, b2, out);
}